// round 12
// baseline (speedup 1.0000x reference)
#include <cuda_runtime.h>
#include <cuda_fp16.h>
#include <stdint.h>

// ---------------- problem constants ----------------
#define HID    256
#define GEO    13
#define DIN    781
#define NBR    4
#define DEPTHL 3
#define EPSB   1e-5f
#define E_CAP  100000

// ---------------- tiling ----------------
#define TM    64
#define NTH   256
#define NG0   49                      // layer-0 k16 groups (49*16=784 >= 781)
#define KPAD0 (NG0*16)
#define NGH   16                      // k16 groups per hidden layer
#define NGT   (NG0 + DEPTHL*NGH)      // 97 groups per branch (linear)
#define KPB   (NGT*16)                // 1552
#define GRP_ELEMS 4096                // 16 ntiles x 32 rows x 8 fp16 (= 8192 B)

// ---------------- smem offsets (bytes) ----------------
#define OFF_SI 0
#define OFF_SJ 256
#define OFF_SK 512
#define OFF_SE 768
#define OFF_H  1024                   // hi plane 32KB + lo plane 32KB
#define OFF_B  (OFF_H + 65536)       // 3 stages x 8KB (fp16 weights, hi only)
#define SMEM_BYTES (OFF_B + 24576)   // 91136  (2 CTA/SM)
// X ring aliases the start of H (dead during layer 0): 2 slots x 4KB

__device__ int g_cnt[NBR];
__device__ int g_list[NBR * E_CAP];
// packed ldmatrix-native fp16 weights: [br][group][ntile][32 rows][8 fp16]
__device__ __align__(16) __half g_W[NBR * NGT * GRP_ELEMS];
// pre-folded BN: scale & shift per [br][layer][col]
__device__ __align__(16) float g_bnS[NBR * (DEPTHL + 1) * HID];
__device__ __align__(16) float g_bnH[NBR * (DEPTHL + 1) * HID];

// ---------------- helpers ----------------
__device__ __forceinline__ uint32_t smem_u32(const void* p) {
    uint32_t a;
    asm("{ .reg .u64 t; cvta.to.shared.u64 t, %1; cvt.u32.u64 %0, t; }" : "=r"(a) : "l"(p));
    return a;
}
__device__ __forceinline__ void cp16(uint32_t dst, const void* src) {
    asm volatile("cp.async.cg.shared.global [%0], [%1], 16;" :: "r"(dst), "l"(src) : "memory");
}
#define CP_COMMIT() asm volatile("cp.async.commit_group;" ::: "memory")
template<int N> __device__ __forceinline__ void cp_wait() {
    asm volatile("cp.async.wait_group %0;" :: "n"(N) : "memory");
}
__device__ __forceinline__ void ldsm4(uint32_t* r, uint32_t a) {
    asm volatile("ldmatrix.sync.aligned.m8n8.x4.shared.b16 {%0,%1,%2,%3}, [%4];"
        : "=r"(r[0]), "=r"(r[1]), "=r"(r[2]), "=r"(r[3]) : "r"(a));
}
__device__ __forceinline__ void mma16816(float* c, const uint32_t* a, const uint32_t* b) {
    asm volatile("mma.sync.aligned.m16n8k16.row.col.f32.f16.f16.f32 "
        "{%0,%1,%2,%3}, {%4,%5,%6,%7}, {%8,%9}, {%0,%1,%2,%3};"
        : "+f"(c[0]), "+f"(c[1]), "+f"(c[2]), "+f"(c[3])
        : "r"(a[0]), "r"(a[1]), "r"(a[2]), "r"(a[3]), "r"(b[0]), "r"(b[1]));
}
// fp16 hi/lo split of two floats, packed
__device__ __forceinline__ void cvt2(float a, float b, uint32_t& h, uint32_t& l) {
    __half ha = __float2half_rn(a), hb = __float2half_rn(b);
    __half la = __float2half_rn(a - __half2float(ha));
    __half lb = __float2half_rn(b - __half2float(hb));
    h = (uint32_t)__half_as_ushort(ha) | ((uint32_t)__half_as_ushort(hb) << 16);
    l = (uint32_t)__half_as_ushort(la) | ((uint32_t)__half_as_ushort(lb) << 16);
}

// ---------------- small kernels ----------------
__global__ void zero_cnt_kernel() {
    if (threadIdx.x < NBR) g_cnt[threadIdx.x] = 0;
}
__global__ void bucket_kernel(const int* __restrict__ edx_ij,
                              const int* __restrict__ edx_jk,
                              const int* __restrict__ nei, int E) {
    int e = blockIdx.x * blockDim.x + threadIdx.x;
    if (e >= E) return;
    int Ein = *nei;
    int br = ((edx_ij[e] < Ein) ? 0 : 2) + ((edx_jk[e] < Ein) ? 0 : 1);
    int pos = atomicAdd(&g_cnt[br], 1);
    g_list[br * E_CAP + pos] = e;
}

// Pack weights transposed into ldmatrix-native fp16 layout.
__global__ void prep_w(const float* __restrict__ W0, const float* __restrict__ Wh) {
    int t = blockIdx.x * blockDim.x + threadIdx.x;
    if (t >= NBR * KPB * HID) return;
    int n = t & 255;
    int rem = t >> 8;
    int k = rem % KPB;
    int br = rem / KPB;
    float w;
    if (k < KPAD0) {
        w = (k < DIN) ? W0[((size_t)br * DIN + k) * HID + n] : 0.f;
    } else {
        int kk = k - KPAD0;
        int l = kk >> 8, k2 = kk & 255;
        w = Wh[(((size_t)(br * DEPTHL + l)) * HID + k2) * HID + n];
    }
    int g  = k >> 4;
    int kl = k & 15;
    int kh = kl >> 3, kb = kl & 7;
    int lrow = (n & 7) + ((n >> 3) & 1) * 16 + kh * 8;
    int ntile = n >> 4;
    size_t off = (((size_t)(br * NGT + g)) * 16 + ntile) * 256 + lrow * 8 + kb;
    g_W[off] = __float2half_rn(w);
}

// Pre-fold BN+bias into scale/shift tables.
__global__ void prep_bn(const float* __restrict__ b0, const float* __restrict__ bh,
                        const float* __restrict__ gamma, const float* __restrict__ beta,
                        const float* __restrict__ rmean, const float* __restrict__ rvar) {
    int t = blockIdx.x * blockDim.x + threadIdx.x;
    if (t >= NBR * (DEPTHL + 1) * HID) return;
    int c = t & 255;
    int rem = t >> 8;
    int layer = rem % (DEPTHL + 1);
    int br = rem / (DEPTHL + 1);
    float sc = gamma[t] * rsqrtf(rvar[t] + EPSB);
    float bias = (layer == 0) ? b0[br * HID + c]
                              : bh[(size_t)(br * DEPTHL + layer - 1) * HID + c];
    g_bnS[t] = sc;
    g_bnH[t] = beta[t] - rmean[t] * sc + bias * sc;
}

__device__ __forceinline__ void prefetch_B(uint32_t smb, int slot, int br, int g, int tid) {
    size_t base = (size_t)(br * NGT + g) * GRP_ELEMS;   // fp16 elems (8192 B)
    uint32_t d = smb + OFF_B + slot * 8192 + (uint32_t)tid * 16;
    const char* s = (const char*)(g_W + base) + tid * 16;
    cp16(d,        s);
    cp16(d + 4096, s + 4096);
}

// Stage layer-0 A chunk kc into X slot (kc&1). tid -> row r=tid>>2, quad q=tid&3.
__device__ __forceinline__ void stage_X(char* sm, int kc,
                                        const float* __restrict__ nf,
                                        const float* __restrict__ geo,
                                        const int* sI, const int* sJ,
                                        const int* sK, const int* sE, int tid) {
    int r = tid >> 2, q = tid & 3;
    float x0, x1, x2, x3;
    if (kc < 48) {
        int seg = kc >> 4;
        int idx = (seg == 0) ? sI[r] : (seg == 1) ? sJ[r] : sK[r];
        const float* src = nf + (size_t)idx * HID + (kc & 15) * 16 + q * 4;
        float4 v = *(const float4*)src;
        x0 = v.x; x1 = v.y; x2 = v.z; x3 = v.w;
    } else {
        int e = sE[r];
        int c0 = q * 4;
        x0 = (c0     < GEO) ? geo[(size_t)e * GEO + c0]     : 0.f;
        x1 = (c0 + 1 < GEO) ? geo[(size_t)e * GEO + c0 + 1] : 0.f;
        x2 = (c0 + 2 < GEO) ? geo[(size_t)e * GEO + c0 + 2] : 0.f;
        x3 = (c0 + 3 < GEO) ? geo[(size_t)e * GEO + c0 + 3] : 0.f;
    }
    uint32_t h0, l0, h1, l1;
    cvt2(x0, x1, h0, l0);
    cvt2(x2, x3, h1, l1);
    int kh = q >> 1;
    int lrow = (r & 7) + ((r >> 3) & 1) * 8 + kh * 16;
    uint32_t off = (uint32_t)((r >> 4) * 512 + lrow * 16 + (q & 1) * 8);
    char* slot = sm + OFF_H + (kc & 1) * 4096;
    *(uint2*)(slot + off)        = make_uint2(h0, h1);
    *(uint2*)(slot + 2048 + off) = make_uint2(l0, l1);
}

// ---------------- main kernel ----------------
__global__ void __launch_bounds__(NTH, 2)
spnn_mma_kernel(const float* __restrict__ nf,
                const float* __restrict__ geo,
                const int*   __restrict__ ei,
                const float* __restrict__ att,
                float* __restrict__ out,
                int E)
{
    const int br  = blockIdx.y;
    const int cnt = g_cnt[br];
    const int m0  = blockIdx.x * TM;
    if (m0 >= cnt) return;

    extern __shared__ char sm[];
    const int tid = threadIdx.x;
    const int wid = tid >> 5, lid = tid & 31;
    const int wm = wid & 1, wn = wid >> 1;   // 2 m-warps x 4 n-warps

    int* sI = (int*)(sm + OFF_SI);
    int* sJ = (int*)(sm + OFF_SJ);
    int* sK = (int*)(sm + OFF_SK);
    int* sE = (int*)(sm + OFF_SE);

    const uint32_t smb = smem_u32(sm);

    if (tid < TM) {
        int idx = m0 + tid;
        int e = (idx < cnt) ? g_list[br * E_CAP + idx] : g_list[br * E_CAP];
        sE[tid] = e;
        sI[tid] = ei[e];
        sJ[tid] = ei[E + e];
        sK[tid] = ei[2 * E + e];
    }

    // prologue: B groups 0 and 1 in flight (slots 0, 1)
    prefetch_B(smb, 0, br, 0, tid);
    CP_COMMIT();
    prefetch_B(smb, 1, br, 1, tid);
    CP_COMMIT();

    __syncthreads();                 // idx visible
    stage_X(sm, 0, nf, geo, sI, sJ, sK, sE, tid);   // X_0 into slot 0

    float acc[2][8][4];
    #pragma unroll
    for (int mt = 0; mt < 2; mt++)
        #pragma unroll
        for (int nt = 0; nt < 8; nt++)
            #pragma unroll
            for (int q = 0; q < 4; q++) acc[mt][nt][q] = 0.f;

    int gidx = 0;

    #pragma unroll 1
    for (int layer = 0; layer <= DEPTHL; layer++) {
        const int nch = (layer == 0) ? NG0 : NGH;

        #pragma unroll 1
        for (int kc = 0; kc < nch; kc++) {
            if (gidx == NGT - 1) cp_wait<0>(); else cp_wait<1>();
            __syncthreads();

            // stage next layer-0 A chunk into the other X slot (no barrier needed)
            if (layer == 0 && kc < NG0 - 1)
                stage_X(sm, kc + 1, nf, geo, sI, sJ, sK, sE, tid);

            // prefetch B group gidx+2 into slot (gidx+2)%3
            if (gidx + 2 < NGT) {
                prefetch_B(smb, (gidx + 2) % 3, br, gidx + 2, tid);
                CP_COMMIT();
            }

            // A fragments (hi + lo planes)
            uint32_t aH, aL;
            if (layer == 0) {
                aH = smb + OFF_H + (uint32_t)((kc & 1) * 4096);
                aL = aH + 2048;
            } else {
                aH = smb + OFF_H + (uint32_t)(kc * 2048);
                aL = aH + 32768;
            }
            uint32_t ahi[2][4], alo[2][4];
            #pragma unroll
            for (int mt = 0; mt < 2; mt++) {
                uint32_t off = (uint32_t)((wm * 2 + mt) * 512 + lid * 16);
                ldsm4(ahi[mt], aH + off);
                ldsm4(alo[mt], aL + off);
            }

            uint32_t bB = smb + OFF_B + (uint32_t)((gidx % 3) * 8192);
            #pragma unroll
            for (int ntp = 0; ntp < 4; ntp++) {
                uint32_t off = (uint32_t)((wn * 4 + ntp) * 512 + lid * 16);
                uint32_t bh4[4];
                ldsm4(bh4, bB + off);
                #pragma unroll
                for (int mt = 0; mt < 2; mt++)
                    #pragma unroll
                    for (int s = 0; s < 2; s++) {
                        float* c = acc[mt][ntp * 2 + s];
                        mma16816(c, ahi[mt], bh4 + s * 2);
                        mma16816(c, alo[mt], bh4 + s * 2);
                    }
            }
            gidx++;
        }

        __syncthreads();   // all reads of H/X done before epilogue writes H

        const bool fin = (layer == DEPTHL);
        const float* bnS = g_bnS + (size_t)(br * (DEPTHL + 1) + layer) * HID;
        const float* bnH = g_bnH + (size_t)(br * (DEPTHL + 1) + layer) * HID;
        float attb = fin ? att[br] : 0.f;

        #pragma unroll
        for (int mt = 0; mt < 2; mt++) {
            int r0 = wm * 32 + mt * 16 + (lid >> 2);
            int r1 = r0 + 8;
            #pragma unroll
            for (int nt = 0; nt < 8; nt++) {
                float* c = acc[mt][nt];
                int j0 = wn * 64 + nt * 8 + (lid & 3) * 2;
                float2 scv = *(const float2*)(bnS + j0);
                float2 shv = *(const float2*)(bnH + j0);
                float f00 = fmaxf(fmaf(c[0], scv.x, shv.x), 0.f);
                float f01 = fmaxf(fmaf(c[1], scv.y, shv.y), 0.f);
                float f10 = fmaxf(fmaf(c[2], scv.x, shv.x), 0.f);
                float f11 = fmaxf(fmaf(c[3], scv.y, shv.y), 0.f);
                c[0] = c[1] = c[2] = c[3] = 0.f;
                if (!fin) {
                    uint32_t hv0, lv0, hv1, lv1;
                    cvt2(f00, f01, hv0, lv0);
                    cvt2(f10, f11, hv1, lv1);
                    int kg = j0 >> 4, kh = (j0 >> 3) & 1;
                    int lr0 = (lid >> 2) + kh * 16;
                    uint32_t base = (uint32_t)(kg * 2048 + (wm * 2 + mt) * 512 + (j0 & 7) * 2);
                    uint32_t o0 = base + (uint32_t)(lr0 * 16);
                    uint32_t o1 = base + (uint32_t)((lr0 + 8) * 16);
                    *(uint32_t*)(sm + OFF_H + o0)         = hv0;
                    *(uint32_t*)(sm + OFF_H + 32768 + o0) = lv0;
                    *(uint32_t*)(sm + OFF_H + o1)         = hv1;
                    *(uint32_t*)(sm + OFF_H + 32768 + o1) = lv1;
                } else {
                    if (m0 + r0 < cnt) {
                        float* op = out + (size_t)sI[r0] * HID + j0;
                        atomicAdd(op,     f00 * attb);
                        atomicAdd(op + 1, f01 * attb);
                    }
                    if (m0 + r1 < cnt) {
                        float* op = out + (size_t)sI[r1] * HID + j0;
                        atomicAdd(op,     f10 * attb);
                        atomicAdd(op + 1, f11 * attb);
                    }
                }
            }
        }
        // next layer's first group sync orders these writes vs. reads
    }
}

extern "C" void kernel_launch(void* const* d_in, const int* in_sizes, int n_in,
                              void* d_out, int out_size) {
    const float* nf  = (const float*)d_in[0];
    const float* geo = (const float*)d_in[1];
    const int*   ei  = (const int*)d_in[2];
    const int*   eij = (const int*)d_in[3];
    const int*   ejk = (const int*)d_in[4];
    const float* att = (const float*)d_in[5];
    const float* W0  = (const float*)d_in[6];
    const float* b0  = (const float*)d_in[7];
    const float* Wh  = (const float*)d_in[8];
    const float* bh  = (const float*)d_in[9];
    const float* gam = (const float*)d_in[10];
    const float* bet = (const float*)d_in[11];
    const float* rme = (const float*)d_in[12];
    const float* rva = (const float*)d_in[13];
    const int*   nei = (const int*)d_in[14];

    int E = in_sizes[3];
    if (E > E_CAP) E = E_CAP;
    float* out = (float*)d_out;

    cudaMemsetAsync(out, 0, (size_t)out_size * sizeof(float));

    zero_cnt_kernel<<<1, 32>>>();
    bucket_kernel<<<(E + 255) / 256, 256>>>(eij, ejk, nei, E);

    int prep_total = NBR * KPB * HID;
    prep_w<<<(prep_total + 255) / 256, 256>>>(W0, Wh);
    int bn_total = NBR * (DEPTHL + 1) * HID;
    prep_bn<<<(bn_total + 255) / 256, 256>>>(b0, bh, gam, bet, rme, rva);

    cudaFuncSetAttribute(spnn_mma_kernel,
                         cudaFuncAttributeMaxDynamicSharedMemorySize, SMEM_BYTES);
    dim3 grid((E + TM - 1) / TM, NBR);
    spnn_mma_kernel<<<grid, NTH, SMEM_BYTES>>>(nf, geo, ei, att, out, E);
}

// round 14
// speedup vs baseline: 1.2547x; 1.2547x over previous
#include <cuda_runtime.h>
#include <cuda_bf16.h>
#include <stdint.h>

// ---------------- problem constants ----------------
#define HID    256
#define GEO    13
#define DIN    781
#define NBR    4
#define DEPTHL 3
#define EPSB   1e-5f
#define E_CAP  100000

// ---------------- tiling ----------------
#define TM    64
#define NTH   256
#define NG0   49                      // layer-0 k16 groups (49*16=784 >= 781)
#define KPAD0 (NG0*16)
#define NGH   16                      // k16 groups per hidden layer
#define NGT   (NG0 + DEPTHL*NGH)      // 97 groups per branch (linear)
#define KPB   (NGT*16)                // 1552
#define GRP_ELEMS 4096                // 16 ntiles x 32 rows x 8 bf16 per plane

// ---------------- smem offsets (bytes) ----------------
#define OFF_SI 0
#define OFF_SJ 256
#define OFF_SK 512
#define OFF_SE 768
#define OFF_H  1024                   // hi plane 32KB + lo plane 32KB
#define OFF_B  (OFF_H + 65536)        // 3 stages x 16KB (hi 8KB + lo 8KB)
#define SMEM_BYTES (OFF_B + 49152)    // 115712 -> 2 CTA/SM
// Layer-0 aliases inside H (dead during layer 0):
//   X bf16 slots: OFF_H + (kc&1)*4096            (2 x 4KB: hi 2KB + lo 2KB each)
#define OFF_RAW (OFF_H + 8192)        //   raw f32 ring: 4 slots x 4KB

__device__ int g_cnt[NBR];
__device__ int g_list[NBR * E_CAP];
// packed ldmatrix-native weights: [br][group][ntile][32 rows][8 bf16]
__device__ __align__(16) __nv_bfloat16 g_Whi[NBR * NGT * GRP_ELEMS];
__device__ __align__(16) __nv_bfloat16 g_Wlo[NBR * NGT * GRP_ELEMS];
// pre-folded BN: scale & shift per [br][layer][col]
__device__ __align__(16) float g_bnS[NBR * (DEPTHL + 1) * HID];
__device__ __align__(16) float g_bnH[NBR * (DEPTHL + 1) * HID];

// ---------------- helpers ----------------
__device__ __forceinline__ uint32_t smem_u32(const void* p) {
    uint32_t a;
    asm("{ .reg .u64 t; cvta.to.shared.u64 t, %1; cvt.u32.u64 %0, t; }" : "=r"(a) : "l"(p));
    return a;
}
__device__ __forceinline__ void cp16(uint32_t dst, const void* src) {
    asm volatile("cp.async.cg.shared.global [%0], [%1], 16;" :: "r"(dst), "l"(src) : "memory");
}
#define CP_COMMIT() asm volatile("cp.async.commit_group;" ::: "memory")
template<int N> __device__ __forceinline__ void cp_wait() {
    asm volatile("cp.async.wait_group %0;" :: "n"(N) : "memory");
}
__device__ __forceinline__ void ldsm4(uint32_t* r, uint32_t a) {
    asm volatile("ldmatrix.sync.aligned.m8n8.x4.shared.b16 {%0,%1,%2,%3}, [%4];"
        : "=r"(r[0]), "=r"(r[1]), "=r"(r[2]), "=r"(r[3]) : "r"(a));
}
__device__ __forceinline__ void mma16816(float* c, const uint32_t* a, const uint32_t* b) {
    asm volatile("mma.sync.aligned.m16n8k16.row.col.f32.bf16.bf16.f32 "
        "{%0,%1,%2,%3}, {%4,%5,%6,%7}, {%8,%9}, {%0,%1,%2,%3};"
        : "+f"(c[0]), "+f"(c[1]), "+f"(c[2]), "+f"(c[3])
        : "r"(a[0]), "r"(a[1]), "r"(a[2]), "r"(a[3]), "r"(b[0]), "r"(b[1]));
}
// bf16 hi/lo split of two floats, packed
__device__ __forceinline__ void cvt2(float a, float b, uint32_t& h, uint32_t& l) {
    __nv_bfloat16 ha = __float2bfloat16(a), hb = __float2bfloat16(b);
    __nv_bfloat16 la = __float2bfloat16(a - __bfloat162float(ha));
    __nv_bfloat16 lb = __float2bfloat16(b - __bfloat162float(hb));
    h = (uint32_t)__bfloat16_as_ushort(ha) | ((uint32_t)__bfloat16_as_ushort(hb) << 16);
    l = (uint32_t)__bfloat16_as_ushort(la) | ((uint32_t)__bfloat16_as_ushort(lb) << 16);
}

// ---------------- fused prep kernel (weights + BN + zero cnt + zero out) ----------------
#define NW (NBR * KPB * HID)
__global__ void prep_all(const float* __restrict__ W0, const float* __restrict__ Wh,
                         const float* __restrict__ b0, const float* __restrict__ bh,
                         const float* __restrict__ gamma, const float* __restrict__ beta,
                         const float* __restrict__ rmean, const float* __restrict__ rvar,
                         float* __restrict__ out, int out_size) {
    int t = blockIdx.x * blockDim.x + threadIdx.x;

    if (t < NBR) g_cnt[t] = 0;

    // zero output (8 floats per thread)
    {
        int base = t * 8;
        if (base + 8 <= out_size) {
            float4 z = make_float4(0.f, 0.f, 0.f, 0.f);
            *(float4*)(out + base)     = z;
            *(float4*)(out + base + 4) = z;
        } else {
            for (int i = base; i < out_size; i++) out[i] = 0.f;
        }
    }

    if (t < NBR * (DEPTHL + 1) * HID) {
        int c = t & 255;
        int rem = t >> 8;
        int layer = rem % (DEPTHL + 1);
        int br = rem / (DEPTHL + 1);
        float sc = gamma[t] * rsqrtf(rvar[t] + EPSB);
        float bias = (layer == 0) ? b0[br * HID + c]
                                  : bh[(size_t)(br * DEPTHL + layer - 1) * HID + c];
        g_bnS[t] = sc;
        g_bnH[t] = beta[t] - rmean[t] * sc + bias * sc;
    }

    if (t < NW) {
        int n = t & 255;
        int rem = t >> 8;
        int k = rem % KPB;
        int br = rem / KPB;
        float w;
        if (k < KPAD0) {
            w = (k < DIN) ? W0[((size_t)br * DIN + k) * HID + n] : 0.f;
        } else {
            int kk = k - KPAD0;
            int l = kk >> 8, k2 = kk & 255;
            w = Wh[(((size_t)(br * DEPTHL + l)) * HID + k2) * HID + n];
        }
        int g  = k >> 4;
        int kl = k & 15;
        int kh = kl >> 3, kb = kl & 7;
        int lrow = (n & 7) + ((n >> 3) & 1) * 16 + kh * 8;
        int ntile = n >> 4;
        size_t off = (((size_t)(br * NGT + g)) * 16 + ntile) * 256 + lrow * 8 + kb;
        __nv_bfloat16 h = __float2bfloat16(w);
        g_Whi[off] = h;
        g_Wlo[off] = __float2bfloat16(w - __bfloat162float(h));
    }
}

__global__ void bucket_kernel(const int* __restrict__ edx_ij,
                              const int* __restrict__ edx_jk,
                              const int* __restrict__ nei, int E) {
    int e = blockIdx.x * blockDim.x + threadIdx.x;
    if (e >= E) return;
    int Ein = *nei;
    int br = ((edx_ij[e] < Ein) ? 0 : 2) + ((edx_jk[e] < Ein) ? 0 : 1);
    int pos = atomicAdd(&g_cnt[br], 1);
    g_list[br * E_CAP + pos] = e;
}

// ---------------- main-kernel device helpers ----------------
__device__ __forceinline__ void prefetch_B(uint32_t smb, int slot, int br, int g, int tid) {
    size_t base = (size_t)(br * NGT + g) * GRP_ELEMS;   // bf16 elems
    uint32_t d = smb + OFF_B + slot * 16384 + (uint32_t)tid * 16;
    const char* sh = (const char*)(g_Whi + base) + tid * 16;
    const char* sl = (const char*)(g_Wlo + base) + tid * 16;
    cp16(d,         sh);
    cp16(d + 4096,  sh + 4096);
    cp16(d + 8192,  sl);
    cp16(d + 12288, sl + 4096);
}

// cp.async one raw f32 node chunk c (1..47) into raw ring slot c&3.
__device__ __forceinline__ void cp_raw(uint32_t smb, int c, const float* __restrict__ nf,
                                       const int* sI, const int* sJ, const int* sK, int tid) {
    int r = tid >> 2, q = tid & 3;
    int seg = c >> 4;
    int idx = (seg == 0) ? sI[r] : (seg == 1) ? sJ[r] : sK[r];
    cp16(smb + OFF_RAW + (c & 3) * 4096 + (uint32_t)(r * 64 + q * 16),
         nf + (size_t)idx * HID + (c & 15) * 16 + q * 4);
}

// Write the (r, q) quad of chunk c into X bf16 slot (c&1) in ldmatrix-native order.
__device__ __forceinline__ void write_X(char* sm, int c, int r, int q,
                                        float x0, float x1, float x2, float x3) {
    uint32_t h0, l0, h1, l1;
    cvt2(x0, x1, h0, l0);
    cvt2(x2, x3, h1, l1);
    int kh = q >> 1;
    int lrow = (r & 7) + ((r >> 3) & 1) * 8 + kh * 16;
    uint32_t off = (uint32_t)((r >> 4) * 512 + lrow * 16 + (q & 1) * 8);
    char* slot = sm + OFF_H + (c & 1) * 4096;
    *(uint2*)(slot + off)        = make_uint2(h0, h1);
    *(uint2*)(slot + 2048 + off) = make_uint2(l0, l1);
}

// cvt chunk c (1..47) from raw ring -> X slot
__device__ __forceinline__ void cvt_X(char* sm, int c, int tid) {
    int r = tid >> 2, q = tid & 3;
    float4 v = *(const float4*)(sm + OFF_RAW + (c & 3) * 4096 + r * 64 + q * 16);
    write_X(sm, c, r, q, v.x, v.y, v.z, v.w);
}

// direct-gmem staging for chunk 0 (nodes) and chunk 48 (geo)
__device__ __forceinline__ void stage_X_direct(char* sm, int kc,
                                               const float* __restrict__ nf,
                                               const float* __restrict__ geo,
                                               const int* sI, const int* sE, int tid) {
    int r = tid >> 2, q = tid & 3;
    float x0, x1, x2, x3;
    if (kc == 0) {
        const float* src = nf + (size_t)sI[r] * HID + q * 4;
        float4 v = *(const float4*)src;
        x0 = v.x; x1 = v.y; x2 = v.z; x3 = v.w;
    } else {
        int e = sE[r];
        int c0 = q * 4;
        x0 = (c0     < GEO) ? geo[(size_t)e * GEO + c0]     : 0.f;
        x1 = (c0 + 1 < GEO) ? geo[(size_t)e * GEO + c0 + 1] : 0.f;
        x2 = (c0 + 2 < GEO) ? geo[(size_t)e * GEO + c0 + 2] : 0.f;
        x3 = (c0 + 3 < GEO) ? geo[(size_t)e * GEO + c0 + 3] : 0.f;
    }
    write_X(sm, kc, r, q, x0, x1, x2, x3);
}

// ---------------- main kernel ----------------
__global__ void __launch_bounds__(NTH, 2)
spnn_mma_kernel(const float* __restrict__ nf,
                const float* __restrict__ geo,
                const int*   __restrict__ ei,
                const float* __restrict__ att,
                float* __restrict__ out,
                int E)
{
    const int br  = blockIdx.y;
    const int cnt = g_cnt[br];
    const int m0  = blockIdx.x * TM;
    if (m0 >= cnt) return;

    extern __shared__ char sm[];
    const int tid = threadIdx.x;
    const int wid = tid >> 5, lid = tid & 31;
    const int wm = wid & 1, wn = wid >> 1;   // 2 m-warps x 4 n-warps

    int* sI = (int*)(sm + OFF_SI);
    int* sJ = (int*)(sm + OFF_SJ);
    int* sK = (int*)(sm + OFF_SK);
    int* sE = (int*)(sm + OFF_SE);

    const uint32_t smb = smem_u32(sm);

    if (tid < TM) {
        int idx = m0 + tid;
        int e = (idx < cnt) ? g_list[br * E_CAP + idx] : g_list[br * E_CAP];
        sE[tid] = e;
        sI[tid] = ei[e];
        sJ[tid] = ei[E + e];
        sK[tid] = ei[2 * E + e];
    }
    __syncthreads();     // indices visible for cp_raw / staging

    // prologue: exactly 2 commit groups in flight at loop entry
    prefetch_B(smb, 0, br, 0, tid);
    cp_raw(smb, 1, nf, sI, sJ, sK, tid);
    CP_COMMIT();                              // {B0, raw1}
    prefetch_B(smb, 1, br, 1, tid);
    cp_raw(smb, 2, nf, sI, sJ, sK, tid);
    CP_COMMIT();                              // {B1, raw2}
    stage_X_direct(sm, 0, nf, geo, sI, sE, tid);   // X slot 0

    float acc[2][8][4];
    #pragma unroll
    for (int mt = 0; mt < 2; mt++)
        #pragma unroll
        for (int nt = 0; nt < 8; nt++)
            #pragma unroll
            for (int q = 0; q < 4; q++) acc[mt][nt][q] = 0.f;

    int gidx = 0;

    #pragma unroll 1
    for (int layer = 0; layer <= DEPTHL; layer++) {
        const int nch = (layer == 0) ? NG0 : NGH;

        #pragma unroll 1
        for (int kc = 0; kc < nch; kc++) {
            cp_wait<1>();        // retires group committed 2 iterations ago
            __syncthreads();

            // layer-0: produce X slot for the NEXT chunk
            if (layer == 0) {
                if (kc + 1 <= 47)      cvt_X(sm, kc + 1, tid);          // from raw ring (LDS)
                else if (kc + 1 == 48) stage_X_direct(sm, 48, nf, geo, sI, sE, tid);
            }

            // exactly one commit group per iteration (possibly empty)
            if (gidx + 2 < NGT)
                prefetch_B(smb, (gidx + 2) % 3, br, gidx + 2, tid);
            if (layer == 0 && kc + 3 <= 47)
                cp_raw(smb, kc + 3, nf, sI, sJ, sK, tid);
            CP_COMMIT();

            // A fragments (hi + lo planes)
            uint32_t aH, aL;
            if (layer == 0) {
                aH = smb + OFF_H + (uint32_t)((kc & 1) * 4096);
                aL = aH + 2048;
            } else {
                aH = smb + OFF_H + (uint32_t)(kc * 2048);
                aL = aH + 32768;
            }
            uint32_t ahi[2][4], alo[2][4];
            #pragma unroll
            for (int mt = 0; mt < 2; mt++) {
                uint32_t off = (uint32_t)((wm * 2 + mt) * 512 + lid * 16);
                ldsm4(ahi[mt], aH + off);
                ldsm4(alo[mt], aL + off);
            }

            uint32_t bB = smb + OFF_B + (uint32_t)((gidx % 3) * 16384);
            #pragma unroll
            for (int ntp = 0; ntp < 4; ntp++) {
                uint32_t off = (uint32_t)((wn * 4 + ntp) * 512 + lid * 16);
                uint32_t bh4[4], bl4[4];
                ldsm4(bh4, bB + off);
                ldsm4(bl4, bB + 8192 + off);
                #pragma unroll
                for (int mt = 0; mt < 2; mt++)
                    #pragma unroll
                    for (int s = 0; s < 2; s++) {
                        float* c = acc[mt][ntp * 2 + s];
                        mma16816(c, ahi[mt], bh4 + s * 2);
                        mma16816(c, alo[mt], bh4 + s * 2);
                        mma16816(c, ahi[mt], bl4 + s * 2);
                    }
            }
            gidx++;
        }

        __syncthreads();   // all reads of H/X done before epilogue writes H

        const bool fin = (layer == DEPTHL);
        const float* bnS = g_bnS + (size_t)(br * (DEPTHL + 1) + layer) * HID;
        const float* bnH = g_bnH + (size_t)(br * (DEPTHL + 1) + layer) * HID;
        float attb = fin ? att[br] : 0.f;

        #pragma unroll
        for (int mt = 0; mt < 2; mt++) {
            int r0 = wm * 32 + mt * 16 + (lid >> 2);
            int r1 = r0 + 8;
            #pragma unroll
            for (int nt = 0; nt < 8; nt++) {
                float* c = acc[mt][nt];
                int j0 = wn * 64 + nt * 8 + (lid & 3) * 2;
                float2 scv = *(const float2*)(bnS + j0);
                float2 shv = *(const float2*)(bnH + j0);
                float f00 = fmaxf(fmaf(c[0], scv.x, shv.x), 0.f);
                float f01 = fmaxf(fmaf(c[1], scv.y, shv.y), 0.f);
                float f10 = fmaxf(fmaf(c[2], scv.x, shv.x), 0.f);
                float f11 = fmaxf(fmaf(c[3], scv.y, shv.y), 0.f);
                c[0] = c[1] = c[2] = c[3] = 0.f;
                if (!fin) {
                    uint32_t hv0, lv0, hv1, lv1;
                    cvt2(f00, f01, hv0, lv0);
                    cvt2(f10, f11, hv1, lv1);
                    int kg = j0 >> 4, kh = (j0 >> 3) & 1;
                    int lr0 = (lid >> 2) + kh * 16;
                    uint32_t base = (uint32_t)(kg * 2048 + (wm * 2 + mt) * 512 + (j0 & 7) * 2);
                    uint32_t o0 = base + (uint32_t)(lr0 * 16);
                    uint32_t o1 = base + (uint32_t)((lr0 + 8) * 16);
                    *(uint32_t*)(sm + OFF_H + o0)         = hv0;
                    *(uint32_t*)(sm + OFF_H + 32768 + o0) = lv0;
                    *(uint32_t*)(sm + OFF_H + o1)         = hv1;
                    *(uint32_t*)(sm + OFF_H + 32768 + o1) = lv1;
                } else {
                    if (m0 + r0 < cnt) {
                        float* op = out + (size_t)sI[r0] * HID + j0;
                        atomicAdd(op,     f00 * attb);
                        atomicAdd(op + 1, f01 * attb);
                    }
                    if (m0 + r1 < cnt) {
                        float* op = out + (size_t)sI[r1] * HID + j0;
                        atomicAdd(op,     f10 * attb);
                        atomicAdd(op + 1, f11 * attb);
                    }
                }
            }
        }
        // next layer's first-group sync orders these writes vs. reads
    }
}

extern "C" void kernel_launch(void* const* d_in, const int* in_sizes, int n_in,
                              void* d_out, int out_size) {
    const float* nf  = (const float*)d_in[0];
    const float* geo = (const float*)d_in[1];
    const int*   ei  = (const int*)d_in[2];
    const int*   eij = (const int*)d_in[3];
    const int*   ejk = (const int*)d_in[4];
    const float* att = (const float*)d_in[5];
    const float* W0  = (const float*)d_in[6];
    const float* b0  = (const float*)d_in[7];
    const float* Wh  = (const float*)d_in[8];
    const float* bh  = (const float*)d_in[9];
    const float* gam = (const float*)d_in[10];
    const float* bet = (const float*)d_in[11];
    const float* rme = (const float*)d_in[12];
    const float* rva = (const float*)d_in[13];
    const int*   nei = (const int*)d_in[14];

    int E = in_sizes[3];
    if (E > E_CAP) E = E_CAP;
    float* out = (float*)d_out;

    // exactly 3 kernel launches per call (helps ncu land on the main kernel)
    int n_zero = (out_size + 7) / 8;
    int total = (NW > n_zero) ? NW : n_zero;
    prep_all<<<(total + 255) / 256, 256>>>(W0, Wh, b0, bh, gam, bet, rme, rva,
                                           out, out_size);
    bucket_kernel<<<(E + 255) / 256, 256>>>(eij, ejk, nei, E);

    cudaFuncSetAttribute(spnn_mma_kernel,
                         cudaFuncAttributeMaxDynamicSharedMemorySize, SMEM_BYTES);
    dim3 grid((E + TM - 1) / TM, NBR);
    spnn_mma_kernel<<<grid, NTH, SMEM_BYTES>>>(nf, geo, ei, att, out, E);
}